// round 5
// baseline (speedup 1.0000x reference)
#include <cuda_runtime.h>

// GAE fused single-pass chunked scan with per-thread decoupled lookback.
// Thread = (env, time-chunk of 16 steps). Local scan kept in registers;
// outputs written exactly once. Compulsory traffic only: 134MB R + 67MB W.

#define T_STEPS 4096
#define NENV    2048
#define NCHUNK  256
#define CHUNK   (T_STEPS / NCHUNK)   // 16

#define GAMMA_C 0.99f
#define GD_C    (0.99f * 0.95f)

__device__ float2 g_PS[NCHUNK * NENV];    // (P, S) aggregate per (chunk, env)
__device__ float  g_incl[NCHUNK * NENV];  // inclusive state entering chunk c-1
__device__ int    g_flag[NCHUNK * NENV];  // 0=empty, 1=aggregate, 2=inclusive

// ---------------------------------------------------------------------------
// Prelude: zero the flags (graph replays reuse the device globals).
// 256*2048 ints = 512K ints = 128K int4.
// ---------------------------------------------------------------------------
__global__ void __launch_bounds__(256) gae_zero_flags()
{
    const int i = blockIdx.x * blockDim.x + threadIdx.x;
    ((int4*)g_flag)[i] = make_int4(0, 0, 0, 0);
}

// ---------------------------------------------------------------------------
// Fused kernel.
// ---------------------------------------------------------------------------
__global__ void __launch_bounds__(256) gae_fused(
    const float* __restrict__ rewards,
    const float* __restrict__ values,
    const float* __restrict__ next_values,
    const int*   __restrict__ next_dones,
    float* __restrict__ adv,
    float* __restrict__ ret)
{
    const int e = blockIdx.x * blockDim.x + threadIdx.x;       // env
    const int c = (NCHUNK - 1) - blockIdx.y;                   // chunk (scan-first = bid 0)
    const int base = ((c + 1) * CHUNK - 1) * NENV + e;         // last timestep of chunk

    // ---- Phase A: local backward scan, state kept in registers ----
    float S[CHUNK];   // local adv with zero incoming state
    float V[CHUNK];   // values (for returns)
    float g = 0.0f, p = 1.0f;
    unsigned int bits = 0u;
    bool alive = true;

    #pragma unroll
    for (int t = 0; t < CHUNK; t++) {                          // t=0 is LAST timestep
        const int idx = base - t * NENV;
        const int   dd = __ldcs(&next_dones[idx]);
        const float rr = __ldcs(&rewards[idx]);
        const float nv = __ldcs(&next_values[idx]);
        const float vv = __ldcs(&values[idx]);

        const float nd = dd ? 0.0f : 1.0f;
        g = (rr + GAMMA_C * nv * nd - vv) + GD_C * nd * g;
        p *= GD_C * nd;
        alive = alive && (dd == 0);
        if (alive) bits |= (1u << t);
        S[t] = g;
        V[t] = vv;
    }

    // ---- Phase B: publish + decoupled lookback along time ----
    const int o = c * NENV + e;
    volatile int* vflag = (volatile int*)g_flag;
    float G;   // state entering this chunk (from later time)

    if (c == NCHUNK - 1) {
        G = 0.0f;
        g_incl[o] = g;                      // inclusive = S (G=0)
        __threadfence();
        vflag[o] = 2;
    } else {
        g_PS[o] = make_float2(p, g);
        __threadfence();
        vflag[o] = 1;

        float accP = 1.0f, accS = 0.0f;
        int w = o + NENV;                   // successor chunk (later time), same env
        while (true) {
            int f = vflag[w];
            while (f == 0) { __nanosleep(40); f = vflag[w]; }
            __threadfence();                // acquire
            if (f == 2) {
                G = accS + accP * __ldcg(&g_incl[w]);
                break;
            }
            const float2 ps = __ldcg(&g_PS[w]);
            accS += accP * ps.y;            // compose aggregate
            accP *= ps.x;
            w += NENV;
        }
        g_incl[o] = g + p * G;              // own inclusive
        __threadfence();
        vflag[o] = 2;
    }

    // ---- Phase C: in-register fixup, stream outputs ----
    float pw = GD_C;
    #pragma unroll
    for (int t = 0; t < CHUNK; t++) {
        const int idx = base - t * NENV;
        const float fix = ((bits >> t) & 1u) ? pw * G : 0.0f;
        const float a = S[t] + fix;
        __stcs(&adv[idx], a);
        __stcs(&ret[idx], a + V[t]);
        pw *= GD_C;
    }
}

// ---------------------------------------------------------------------------
// Launch
// ---------------------------------------------------------------------------
extern "C" void kernel_launch(void* const* d_in, const int* in_sizes, int n_in,
                              void* d_out, int out_size)
{
    const float* rewards     = (const float*)d_in[0];
    const float* values      = (const float*)d_in[1];
    const float* next_values = (const float*)d_in[2];
    const int*   next_dones  = (const int*)d_in[3];

    float* adv = (float*)d_out;
    float* ret = (float*)d_out + (size_t)T_STEPS * NENV;

    gae_zero_flags<<<(NCHUNK * NENV / 4) / 256, 256>>>();

    dim3 block(256);
    dim3 grid(NENV / 256, NCHUNK);   // (8, 256) = 2048 blocks; blockIdx.y=0 -> c=255
    gae_fused<<<grid, block>>>(rewards, values, next_values, next_dones, adv, ret);
}

// round 6
// speedup vs baseline: 1.3098x; 1.3098x over previous
#include <cuda_runtime.h>

// GAE 3-pass chunked scan, v6: minimum-DRAM-traffic variant.
// Pass1 (x4 env vector): local backward scan; writes ONLY S-scratch (33.5MB)
//   + (P,S) summaries + nodone bitmask. r/nv/dones streamed (__ldcs, evict-
//   first); v read with default policy so it stays L2-resident for pass3.
// Pass2: per-env scan over 128 chunk summaries (register-prefetched).
// Pass3 (x4 env vector): adv = S + fix, ret = adv + v. Reads S-scratch and v
//   from L2; streams outputs with __stcs.

#define T_STEPS 4096
#define NENV    2048
#define NCHUNK  128
#define CHUNK   (T_STEPS / NCHUNK)   // 32
#define NE4     (NENV / 4)           // 512 float4 lanes per timestep

#define GAMMA_C 0.99f
#define GD_C    (0.99f * 0.95f)

__device__ float        g_Sscratch[T_STEPS * NENV]; // local adv (zero incoming state)
__device__ float2       g_PS[NCHUNK * NENV];        // (P, S) per chunk,env
__device__ float        g_G[NCHUNK * NENV];         // incoming state per chunk
__device__ unsigned int g_bits[NCHUNK * NENV];      // suffix-nodone bitmask

// ---------------------------------------------------------------------------
// Pass 1: thread handles 4 consecutive envs. t=0 is the LAST timestep.
// ---------------------------------------------------------------------------
__global__ void __launch_bounds__(256) gae_pass1(
    const float4* __restrict__ rewards,
    const float4* __restrict__ values,
    const float4* __restrict__ next_values,
    const int4*   __restrict__ next_dones)
{
    const int e4 = blockIdx.x * blockDim.x + threadIdx.x;   // env-quad index
    const int c  = blockIdx.y;
    const int base = ((c + 1) * CHUNK - 1) * NE4 + e4;

    float g0 = 0.f, g1 = 0.f, g2 = 0.f, g3 = 0.f;
    float p0 = 1.f, p1 = 1.f, p2 = 1.f, p3 = 1.f;
    unsigned int b0 = 0u, b1 = 0u, b2 = 0u, b3 = 0u;
    bool a0 = true, a1 = true, a2 = true, a3 = true;

    float4* Ss = (float4*)g_Sscratch;

    #pragma unroll 8
    for (int t = 0; t < CHUNK; t++) {
        const int idx = base - t * NE4;
        const int4   d  = __ldcs(&next_dones[idx]);
        const float4 r  = __ldcs(&rewards[idx]);
        const float4 nv = __ldcs(&next_values[idx]);
        const float4 v  = values[idx];                 // default: keep in L2

        const float nd0 = d.x ? 0.f : 1.f;
        const float nd1 = d.y ? 0.f : 1.f;
        const float nd2 = d.z ? 0.f : 1.f;
        const float nd3 = d.w ? 0.f : 1.f;
        g0 = (r.x + GAMMA_C * nv.x * nd0 - v.x) + GD_C * nd0 * g0;
        g1 = (r.y + GAMMA_C * nv.y * nd1 - v.y) + GD_C * nd1 * g1;
        g2 = (r.z + GAMMA_C * nv.z * nd2 - v.z) + GD_C * nd2 * g2;
        g3 = (r.w + GAMMA_C * nv.w * nd3 - v.w) + GD_C * nd3 * g3;
        p0 *= GD_C * nd0;  p1 *= GD_C * nd1;
        p2 *= GD_C * nd2;  p3 *= GD_C * nd3;
        a0 = a0 && (d.x == 0);  a1 = a1 && (d.y == 0);
        a2 = a2 && (d.z == 0);  a3 = a3 && (d.w == 0);
        if (a0) b0 |= (1u << t);
        if (a1) b1 |= (1u << t);
        if (a2) b2 |= (1u << t);
        if (a3) b3 |= (1u << t);

        Ss[idx] = make_float4(g0, g1, g2, g3);         // default: keep in L2
    }

    const int o = c * NENV + 4 * e4;
    *(float4*)&g_PS[o]     = make_float4(p0, g0, p1, g1);
    *(float4*)&g_PS[o + 2] = make_float4(p2, g2, p3, g3);
    *(uint4*)&g_bits[o]    = make_uint4(b0, b1, b2, b3);
}

// ---------------------------------------------------------------------------
// Pass 2: per-env reverse scan over chunks; prefetch 16 summaries per tile.
// ---------------------------------------------------------------------------
__global__ void __launch_bounds__(256) gae_pass2()
{
    const int e = blockIdx.x * blockDim.x + threadIdx.x;
    float g = 0.0f;
    #pragma unroll
    for (int tile = NCHUNK / 16 - 1; tile >= 0; tile--) {
        float2 ps[16];
        #pragma unroll
        for (int i = 0; i < 16; i++)
            ps[i] = g_PS[(tile * 16 + i) * NENV + e];
        #pragma unroll
        for (int i = 15; i >= 0; i--) {
            const int o = (tile * 16 + i) * NENV + e;
            g_G[o] = g;                    // state entering chunk (from later time)
            g = ps[i].y + ps[i].x * g;     // S + P*g
        }
    }
}

// ---------------------------------------------------------------------------
// Pass 3: adv = S + fix, ret = adv + v. fix = bit(t) * gd^(t+1) * G.
// Thread handles 4 consecutive envs. Reads hit L2; outputs streamed.
// ---------------------------------------------------------------------------
__global__ void __launch_bounds__(256) gae_pass3(
    const float4* __restrict__ values,
    float4* __restrict__ adv,
    float4* __restrict__ ret)
{
    const int e4 = blockIdx.x * blockDim.x + threadIdx.x;
    const int c  = blockIdx.y;
    const int o  = c * NENV + 4 * e4;
    const int base = ((c + 1) * CHUNK - 1) * NE4 + e4;

    const float4 G = *(const float4*)&g_G[o];
    const uint4  B = *(const uint4*)&g_bits[o];
    const float4* Ss = (const float4*)g_Sscratch;

    float pw = GD_C;
    #pragma unroll 8
    for (int t = 0; t < CHUNK; t++) {
        const int idx = base - t * NE4;
        const float4 s = Ss[idx];
        const float4 v = values[idx];
        float4 a;
        a.x = s.x + (((B.x >> t) & 1u) ? pw * G.x : 0.0f);
        a.y = s.y + (((B.y >> t) & 1u) ? pw * G.y : 0.0f);
        a.z = s.z + (((B.z >> t) & 1u) ? pw * G.z : 0.0f);
        a.w = s.w + (((B.w >> t) & 1u) ? pw * G.w : 0.0f);
        float4 rr = make_float4(a.x + v.x, a.y + v.y, a.z + v.z, a.w + v.w);
        __stcs(&adv[idx], a);
        __stcs(&ret[idx], rr);
        pw *= GD_C;
    }
}

// ---------------------------------------------------------------------------
// Launch
// ---------------------------------------------------------------------------
extern "C" void kernel_launch(void* const* d_in, const int* in_sizes, int n_in,
                              void* d_out, int out_size)
{
    const float4* rewards     = (const float4*)d_in[0];
    const float4* values      = (const float4*)d_in[1];
    const float4* next_values = (const float4*)d_in[2];
    const int4*   next_dones  = (const int4*)d_in[3];

    float4* adv = (float4*)d_out;
    float4* ret = (float4*)((float*)d_out + (size_t)T_STEPS * NENV);

    dim3 block(256);
    dim3 grid1(NE4 / 256, NCHUNK);   // (2, 128) = 256 blocks

    gae_pass1<<<grid1, block>>>(rewards, values, next_values, next_dones);
    gae_pass2<<<NENV / 256, block>>>();
    gae_pass3<<<grid1, block>>>(values, adv, ret);
}

// round 7
// speedup vs baseline: 1.6753x; 1.2791x over previous
#include <cuda_runtime.h>

// GAE fused single-pass scan, v7: per-thread aggregate-only decoupled lookback
// with geometric early termination (accP < 1e-12 after ~9 chunk hops).
// Thread = (env, 32-step chunk). S,V register-resident; outputs written once.
// DRAM traffic = compulsory 134MB read + 67MB write.

#define T_STEPS 4096
#define NENV    2048
#define NCHUNK  128
#define CHUNK   32

#define GAMMA_C 0.99f
#define GD_C    (0.99f * 0.95f)

__device__ float2 g_PS[NCHUNK * NENV];   // (P, S) aggregate per (chunk, env)
__device__ int    g_flag[NCHUNK * NENV]; // 0 = empty, 1 = aggregate published

// ---------------------------------------------------------------------------
// Prelude: zero flags (device globals persist across graph replays).
// 128*2048 ints = 256K ints = 64K int4 -> 256 blocks x 256 threads.
// ---------------------------------------------------------------------------
__global__ void __launch_bounds__(256) gae_zero_flags()
{
    const int i = blockIdx.x * blockDim.x + threadIdx.x;
    ((int4*)g_flag)[i] = make_int4(0, 0, 0, 0);
}

// ---------------------------------------------------------------------------
// Fused kernel.
// ---------------------------------------------------------------------------
__global__ void __launch_bounds__(256) gae_fused(
    const float* __restrict__ rewards,
    const float* __restrict__ values,
    const float* __restrict__ next_values,
    const int*   __restrict__ next_dones,
    float* __restrict__ adv,
    float* __restrict__ ret)
{
    const int e = blockIdx.x * blockDim.x + threadIdx.x;   // env
    const int c = (NCHUNK - 1) - blockIdx.y;               // latest chunk = bid 0
    const int base = ((c + 1) * CHUNK - 1) * NENV + e;     // last timestep of chunk

    // ---- Phase A: local backward scan, state register-resident ----
    float S[CHUNK];
    float V[CHUNK];
    float g = 0.0f, p = 1.0f;
    unsigned int bits = 0u;
    bool alive = true;

    #pragma unroll
    for (int t = 0; t < CHUNK; t++) {                      // t=0 is LAST timestep
        const int idx = base - t * NENV;
        const int   dd = __ldcs(&next_dones[idx]);
        const float rr = __ldcs(&rewards[idx]);
        const float nv = __ldcs(&next_values[idx]);
        const float vv = __ldcs(&values[idx]);

        const float nd = dd ? 0.0f : 1.0f;
        g = (rr + GAMMA_C * nv * nd - vv) + GD_C * nd * g;
        p *= GD_C * nd;
        alive = alive && (dd == 0);
        if (alive) bits |= (1u << t);
        S[t] = g;
        V[t] = vv;
    }

    // ---- Publish aggregate ----
    const int o = c * NENV + e;
    g_PS[o] = make_float2(p, g);
    __threadfence();
    ((volatile int*)g_flag)[o] = 1;

    // ---- Phase B: compose G from later chunks' aggregates (no inclusive chain)
    // accP *= gd^32 (=0.14) per hop, or 0 at any done -> walk terminates fast.
    float G = 0.0f;
    if (c < NCHUNK - 1) {
        float accP = 1.0f, accS = 0.0f;
        int w = c + 1;
        while (w < NCHUNK && accP > 1e-12f) {
            const int nb = (NCHUNK - w < 8) ? (NCHUNK - w) : 8;
            // wait until the whole tile of aggregates is published
            bool ok;
            do {
                ok = true;
                #pragma unroll
                for (int i = 0; i < 8; i++)
                    if (i < nb)
                        ok = ok && (((volatile int*)g_flag)[(w + i) * NENV + e] != 0);
                if (!ok) __nanosleep(50);
            } while (!ok);
            __threadfence();   // acquire: order flag read before data reads

            float2 ps[8];
            #pragma unroll
            for (int i = 0; i < 8; i++)
                if (i < nb) ps[i] = __ldcg(&g_PS[(w + i) * NENV + e]);
            #pragma unroll
            for (int i = 0; i < 8; i++)
                if (i < nb) {
                    accS += accP * ps[i].y;   // compose f_w: x -> S_w + P_w*x
                    accP *= ps[i].x;
                }
            w += nb;
        }
        G = accS;
    }

    // ---- Phase C: in-register fixup, stream outputs exactly once ----
    float pw = GD_C;
    #pragma unroll
    for (int t = 0; t < CHUNK; t++) {
        const int idx = base - t * NENV;
        const float fix = ((bits >> t) & 1u) ? pw * G : 0.0f;
        const float a = S[t] + fix;
        __stcs(&adv[idx], a);
        __stcs(&ret[idx], a + V[t]);
        pw *= GD_C;
    }
}

// ---------------------------------------------------------------------------
// Launch
// ---------------------------------------------------------------------------
extern "C" void kernel_launch(void* const* d_in, const int* in_sizes, int n_in,
                              void* d_out, int out_size)
{
    const float* rewards     = (const float*)d_in[0];
    const float* values      = (const float*)d_in[1];
    const float* next_values = (const float*)d_in[2];
    const int*   next_dones  = (const int*)d_in[3];

    float* adv = (float*)d_out;
    float* ret = (float*)d_out + (size_t)T_STEPS * NENV;

    gae_zero_flags<<<(NCHUNK * NENV / 4) / 256, 256>>>();

    dim3 block(256);
    dim3 grid(NENV / 256, NCHUNK);   // (8, 128) = 1024 blocks
    gae_fused<<<grid, block>>>(rewards, values, next_values, next_dones, adv, ret);
}

// round 8
// speedup vs baseline: 1.7994x; 1.0741x over previous
#include <cuda_runtime.h>

// GAE fused single-pass scan, v8.
// - S[] in shared memory (32KB/block), V dropped (v reloaded from L2 in
//   phase C) -> regs ~60, occupancy smem-limited ~85%.
// - Epoch-based lookback flags: no flag-array zeroing, just a 1-thread bump.
// - Lookback: dones ~ Bernoulli(0.5) => chunk P=0 almost surely; walk
//   terminates after ~1 hop. Phase B is latency-trivial.

#define T_STEPS 4096
#define NENV    2048
#define NCHUNK  128
#define CHUNK   32

#define GAMMA_C 0.99f
#define GD_C    (0.99f * 0.95f)

__device__ float2 g_PS[NCHUNK * NENV];    // (P, S) aggregate per (chunk, env)
__device__ int    g_flag[NCHUNK * NENV];  // == g_epoch when published
__device__ int    g_epoch = 0;

// ---------------------------------------------------------------------------
__global__ void gae_bump_epoch() { g_epoch += 1; }

// ---------------------------------------------------------------------------
__global__ void __launch_bounds__(256) gae_fused(
    const float* __restrict__ rewards,
    const float* __restrict__ values,
    const float* __restrict__ next_values,
    const int*   __restrict__ next_dones,
    float* __restrict__ adv,
    float* __restrict__ ret)
{
    __shared__ float sS[CHUNK * 256];                      // S[t] per thread

    const int tid = threadIdx.x;
    const int e = blockIdx.x * blockDim.x + tid;           // env
    const int c = (NCHUNK - 1) - blockIdx.y;               // latest chunk = bid 0
    const int base = ((c + 1) * CHUNK - 1) * NENV + e;     // last timestep of chunk
    const int epoch = *(volatile int*)&g_epoch;

    // ---- Phase A: local backward scan; S -> smem; v default (stays in L2) ----
    float g = 0.0f, p = 1.0f;
    unsigned int bits = 0u;
    bool alive = true;

    #pragma unroll 8
    for (int t = 0; t < CHUNK; t++) {                      // t=0 is LAST timestep
        const int idx = base - t * NENV;
        const int   dd = __ldcs(&next_dones[idx]);
        const float rr = __ldcs(&rewards[idx]);
        const float nv = __ldcs(&next_values[idx]);
        const float vv = values[idx];                      // keep in L2 for phase C

        const float nd = dd ? 0.0f : 1.0f;
        g = (rr + GAMMA_C * nv * nd - vv) + GD_C * nd * g;
        p *= GD_C * nd;
        alive = alive && (dd == 0);
        if (alive) bits |= (1u << t);
        sS[t * 256 + tid] = g;
    }

    // ---- Publish aggregate ----
    const int o = c * NENV + e;
    g_PS[o] = make_float2(p, g);
    __threadfence();
    ((volatile int*)g_flag)[o] = epoch;

    // ---- Phase B: compose G from later chunks' aggregates ----
    float G = 0.0f;
    if (c < NCHUNK - 1) {
        float accP = 1.0f, accS = 0.0f;
        int w = o + NENV;                                  // next-later chunk, same env
        const int wend = NCHUNK * NENV;
        while (w < wend && accP > 1e-12f) {
            while (((volatile int*)g_flag)[w] != epoch) __nanosleep(40);
            __threadfence();                               // acquire
            const float2 ps = __ldcg(&g_PS[w]);
            accS += accP * ps.y;
            accP *= ps.x;
            w += NENV;
        }
        G = accS;
    }

    // ---- Phase C: fixup from smem, reload v (L2 hit), stream outputs ----
    float pw = GD_C;
    #pragma unroll 8
    for (int t = 0; t < CHUNK; t++) {
        const int idx = base - t * NENV;
        const float fix = ((bits >> t) & 1u) ? pw * G : 0.0f;
        const float a = sS[t * 256 + tid] + fix;
        __stcs(&adv[idx], a);
        __stcs(&ret[idx], a + values[idx]);
        pw *= GD_C;
    }
}

// ---------------------------------------------------------------------------
extern "C" void kernel_launch(void* const* d_in, const int* in_sizes, int n_in,
                              void* d_out, int out_size)
{
    const float* rewards     = (const float*)d_in[0];
    const float* values      = (const float*)d_in[1];
    const float* next_values = (const float*)d_in[2];
    const int*   next_dones  = (const int*)d_in[3];

    float* adv = (float*)d_out;
    float* ret = (float*)d_out + (size_t)T_STEPS * NENV;

    gae_bump_epoch<<<1, 1>>>();

    dim3 block(256);
    dim3 grid(NENV / 256, NCHUNK);   // (8, 128) = 1024 blocks
    gae_fused<<<grid, block>>>(rewards, values, next_values, next_dones, adv, ret);
}

// round 9
// speedup vs baseline: 1.8823x; 1.0461x over previous
#include <cuda_runtime.h>

// GAE fused single-pass scan, v9: CHUNK 32 -> 16.
// smem 16KB/block => 8 blocks/SM (warp-capped, ~100% occ ceiling).
// Lookback walk terminates at first dead chunk (~1-2 hops at p(done)=0.5).

#define T_STEPS 4096
#define NENV    2048
#define NCHUNK  256
#define CHUNK   16

#define GAMMA_C 0.99f
#define GD_C    (0.99f * 0.95f)

__device__ float2 g_PS[NCHUNK * NENV];    // (P, S) aggregate per (chunk, env)
__device__ int    g_flag[NCHUNK * NENV];  // == g_epoch when published
__device__ int    g_epoch = 0;

// ---------------------------------------------------------------------------
__global__ void gae_bump_epoch() { g_epoch += 1; }

// ---------------------------------------------------------------------------
__global__ void __launch_bounds__(256) gae_fused(
    const float* __restrict__ rewards,
    const float* __restrict__ values,
    const float* __restrict__ next_values,
    const int*   __restrict__ next_dones,
    float* __restrict__ adv,
    float* __restrict__ ret)
{
    __shared__ float sS[CHUNK * 256];                      // 16KB

    const int tid = threadIdx.x;
    const int e = blockIdx.x * blockDim.x + tid;           // env
    const int c = (NCHUNK - 1) - blockIdx.y;               // latest chunk = bid 0
    const int base = ((c + 1) * CHUNK - 1) * NENV + e;     // last timestep of chunk
    const int epoch = *(volatile int*)&g_epoch;

    // ---- Phase A: local backward scan; S -> smem; v default (stays in L2) ----
    float g = 0.0f, p = 1.0f;
    unsigned int bits = 0u;
    bool alive = true;

    #pragma unroll
    for (int t = 0; t < CHUNK; t++) {                      // t=0 is LAST timestep
        const int idx = base - t * NENV;
        const int   dd = __ldcs(&next_dones[idx]);
        const float rr = __ldcs(&rewards[idx]);
        const float nv = __ldcs(&next_values[idx]);
        const float vv = values[idx];                      // keep in L2 for phase C

        const float nd = dd ? 0.0f : 1.0f;
        g = (rr + GAMMA_C * nv * nd - vv) + GD_C * nd * g;
        p *= GD_C * nd;
        alive = alive && (dd == 0);
        if (alive) bits |= (1u << t);
        sS[t * 256 + tid] = g;
    }

    // ---- Publish aggregate ----
    const int o = c * NENV + e;
    g_PS[o] = make_float2(p, g);
    __threadfence();
    ((volatile int*)g_flag)[o] = epoch;

    // ---- Phase B: compose G from later chunks' aggregates ----
    float G = 0.0f;
    if (c < NCHUNK - 1) {
        float accP = 1.0f, accS = 0.0f;
        int w = o + NENV;                                  // next-later chunk, same env
        const int wend = NCHUNK * NENV;
        while (w < wend && accP > 1e-12f) {
            while (((volatile int*)g_flag)[w] != epoch) __nanosleep(40);
            __threadfence();                               // acquire
            const float2 ps = __ldcg(&g_PS[w]);
            accS += accP * ps.y;
            accP *= ps.x;
            w += NENV;
        }
        G = accS;
    }

    // ---- Phase C: fixup from smem, reload v (L2 hit), stream outputs ----
    float pw = GD_C;
    #pragma unroll
    for (int t = 0; t < CHUNK; t++) {
        const int idx = base - t * NENV;
        const float fix = ((bits >> t) & 1u) ? pw * G : 0.0f;
        const float a = sS[t * 256 + tid] + fix;
        __stcs(&adv[idx], a);
        __stcs(&ret[idx], a + values[idx]);
        pw *= GD_C;
    }
}

// ---------------------------------------------------------------------------
extern "C" void kernel_launch(void* const* d_in, const int* in_sizes, int n_in,
                              void* d_out, int out_size)
{
    const float* rewards     = (const float*)d_in[0];
    const float* values      = (const float*)d_in[1];
    const float* next_values = (const float*)d_in[2];
    const int*   next_dones  = (const int*)d_in[3];

    float* adv = (float*)d_out;
    float* ret = (float*)d_out + (size_t)T_STEPS * NENV;

    gae_bump_epoch<<<1, 1>>>();

    dim3 block(256);
    dim3 grid(NENV / 256, NCHUNK);   // (8, 256) = 2048 blocks
    gae_fused<<<grid, block>>>(rewards, values, next_values, next_dones, adv, ret);
}